// round 8
// baseline (speedup 1.0000x reference)
#include <cuda_runtime.h>
#include <cuda_bf16.h>

#define NUM_NODES 5000
#define NUM_EDGES 80000
#define BS        2048      // BATCH * SEQ
#define OUTF      10
#define BKT_CAP   128       // max in-degree capacity (Poisson(16): P(>128) ~ 1e-60)
#define TPB       256
#define NBLOCKS   592       // 148 SMs x 4 blocks/SM -> all resident (grid-barrier safe)
#define NFL4      (BS * 2 * OUTF / 4)      // 10240 float4 per node
#define SITERS    (NFL4 / TPB)             // 40 store iterations per node

// Scratch (allocation-free). g_cnt is zero-initialized at module load and
// self-cleaning: the node phase resets it after consuming, so every call
// (correctness run, capture, every replay) sees g_cnt == 0 on entry.
__device__ int g_cnt[NUM_NODES];
__device__ int g_bkt[NUM_NODES * BKT_CAP];

// Grid barrier state. g_epoch is monotonic across launches (replay-safe);
// g_arrive self-resets to 0 each barrier passage.
__device__ unsigned g_arrive;
__device__ unsigned g_epoch;

__device__ __forceinline__ void grid_sync() {
    __syncthreads();
    if (threadIdx.x == 0) {
        __threadfence();
        unsigned e = *(volatile unsigned*)&g_epoch;   // read BEFORE arriving
        if (atomicAdd(&g_arrive, 1) == NBLOCKS - 1) {
            g_arrive = 0;
            __threadfence();
            atomicAdd(&g_epoch, 1);                   // release
        } else {
            while (*(volatile unsigned*)&g_epoch == e) { __nanosleep(64); }
        }
        __threadfence();
    }
    __syncthreads();
}

__global__ __launch_bounds__(TPB, 4) void k_fused(const float* __restrict__ f,
                                                  const float* __restrict__ w,
                                                  const int*   __restrict__ esrc,
                                                  const int*   __restrict__ edst,
                                                  float* __restrict__ out) {
    const int tid = threadIdx.x;

    __shared__ float sw[2 * OUTF];     // duplicated weight table: sw[c] = w[c % 10]
    __shared__ float s_self[BS];
    __shared__ float s_mean[BS];
    __shared__ int   sedge[BKT_CAP];

    // ---- Phase 1: bucket edges by destination (592*256 threads >= 80000) ----
    {
        int i = blockIdx.x * TPB + tid;
        if (i < NUM_EDGES) {
            int d = edst[i];
            int pos = atomicAdd(&g_cnt[d], 1);
            if (pos < BKT_CAP) g_bkt[d * BKT_CAP + pos] = esrc[i];
        }
    }
    if (tid < OUTF) { float wv = w[tid]; sw[tid] = wv; sw[tid + OUTF] = wv; }

    grid_sync();

    // ---- Phase 2: grid-stride node loop (R5 body) ----
    for (int n = blockIdx.x; n < NUM_NODES; n += NBLOCKS) {
        const int deg = min(g_cnt[n], BKT_CAP);
        const float inv = (deg > 0) ? (1.0f / (float)deg) : 0.0f;

        if (tid < deg) sedge[tid] = g_bkt[n * BKT_CAP + tid];
        __syncthreads();                       // sedge ready; prior stores done

        if (tid == 0) g_cnt[n] = 0;            // self-clean for next replay

        // Two independent float4 lanes per thread: tid and tid+TPB (of 512 lanes).
        float4 acc0 = make_float4(0.f, 0.f, 0.f, 0.f);
        float4 acc1 = make_float4(0.f, 0.f, 0.f, 0.f);
        #pragma unroll 4
        for (int j = 0; j < deg; j++) {
            const float4* row = (const float4*)(f + (size_t)sedge[j] * BS);
            float4 v0 = __ldg(row + tid);
            float4 v1 = __ldg(row + tid + TPB);
            acc0.x += v0.x; acc0.y += v0.y; acc0.z += v0.z; acc0.w += v0.w;
            acc1.x += v1.x; acc1.y += v1.y; acc1.z += v1.z; acc1.w += v1.w;
        }

        const float4* selfrow = (const float4*)(f + (size_t)n * BS);
        float4 self0 = __ldg(selfrow + tid);
        float4 self1 = __ldg(selfrow + tid + TPB);

        __syncthreads();                       // prior iter's smem readers done
        ((float4*)s_self)[tid]       = self0;
        ((float4*)s_self)[tid + TPB] = self1;
        ((float4*)s_mean)[tid]       = make_float4(acc0.x*inv, acc0.y*inv, acc0.z*inv, acc0.w*inv);
        ((float4*)s_mean)[tid + TPB] = make_float4(acc1.x*inv, acc1.y*inv, acc1.z*inv, acc1.w*inv);
        __syncthreads();

        // Coalesced streaming stores: 10240 float4s for this node.
        // float4 idx -> bs = idx/5; channels (idx%5)*4 .. +3.
        float4* ob = (float4*)out + (size_t)n * NFL4;
        #pragma unroll
        for (int it = 0; it < SITERS; it++) {
            int idx = it * TPB + tid;
            int bs  = idx / 5;
            int c0  = (idx % 5) * 4;
            float s = s_self[bs];
            float m = s_mean[bs];
            float4 r;
            { int c = c0 + 0; float b = (c < OUTF) ? s : m; r.x = fmaxf(b * sw[c], 0.0f); }
            { int c = c0 + 1; float b = (c < OUTF) ? s : m; r.y = fmaxf(b * sw[c], 0.0f); }
            { int c = c0 + 2; float b = (c < OUTF) ? s : m; r.z = fmaxf(b * sw[c], 0.0f); }
            { int c = c0 + 3; float b = (c < OUTF) ? s : m; r.w = fmaxf(b * sw[c], 0.0f); }
            __stcs(ob + idx, r);   // evict-first: keep features resident in L2
        }
    }
}

extern "C" void kernel_launch(void* const* d_in, const int* in_sizes, int n_in,
                              void* d_out, int out_size) {
    const float* features = (const float*)d_in[0];
    const float* weight   = (const float*)d_in[1];
    const int*   edge_src = (const int*)d_in[2];
    const int*   edge_dst = (const int*)d_in[3];
    float*       out      = (float*)d_out;

    k_fused<<<NBLOCKS, TPB>>>(features, weight, edge_src, edge_dst, out);
}

// round 9
// speedup vs baseline: 1.8512x; 1.8512x over previous
#include <cuda_runtime.h>
#include <cuda_bf16.h>

#define NUM_NODES 5000
#define NUM_EDGES 80000
#define BS        2048      // BATCH * SEQ
#define OUTF      10
#define BKT_CAP   128       // max in-degree capacity (Poisson(16): P(>128) ~ 1e-60)
#define TPB       256
#define NFL4      (BS * 2 * OUTF / 4)      // 10240 float4 per node
#define SITERS    (NFL4 / TPB)             // 40 store iterations per node

// Scratch (allocation-free). g_cnt is zero-initialized at module load and
// self-cleaning: k_main resets g_cnt[n] after consuming it, so every call
// (correctness run, capture, every replay) sees g_cnt == 0 on entry.
__device__ int g_cnt[NUM_NODES];
__device__ int g_bkt[NUM_NODES * BKT_CAP];

__global__ void k_bucket(const int* __restrict__ src, const int* __restrict__ dst) {
    int i = blockIdx.x * blockDim.x + threadIdx.x;
    if (i < NUM_EDGES) {
        int d = dst[i];
        int pos = atomicAdd(&g_cnt[d], 1);
        if (pos < BKT_CAP) g_bkt[d * BKT_CAP + pos] = src[i];
    }
}

// One block per node.
// Phase 1: gather+mean into shared (thread owns 2 float4 lanes -> 2 indep load chains).
// Phase 2: fully-coalesced streaming output writes.
__global__ __launch_bounds__(TPB) void k_main(const float* __restrict__ f,
                                              const float* __restrict__ w,
                                              float* __restrict__ out) {
    const int n   = blockIdx.x;
    const int tid = threadIdx.x;

    __shared__ float sw[2 * OUTF];     // duplicated weight table: sw[c] = w[c % 10]
    __shared__ float s_self[BS];
    __shared__ float s_mean[BS];
    __shared__ int   sedge[BKT_CAP];

    if (tid < OUTF) { float wv = w[tid]; sw[tid] = wv; sw[tid + OUTF] = wv; }

    const int deg = min(g_cnt[n], BKT_CAP);
    const float inv = (deg > 0) ? (1.0f / (float)deg) : 0.0f;

    if (tid < deg) sedge[tid] = g_bkt[n * BKT_CAP + tid];
    __syncthreads();

    // Reset counter for the next graph replay (all reads of g_cnt[n] are done).
    if (tid == 0) g_cnt[n] = 0;

    // Self-row loads issued BEFORE the gather loop: independent, in flight early.
    const float4* selfrow = (const float4*)(f + (size_t)n * BS);
    float4 self0 = __ldg(selfrow + tid);
    float4 self1 = __ldg(selfrow + tid + TPB);

    // Two independent float4 lanes per thread: tid and tid+TPB (of BS/4=512 lanes).
    float4 acc0 = make_float4(0.f, 0.f, 0.f, 0.f);
    float4 acc1 = make_float4(0.f, 0.f, 0.f, 0.f);
    #pragma unroll 4
    for (int j = 0; j < deg; j++) {
        const float4* row = (const float4*)(f + (size_t)sedge[j] * BS);
        float4 v0 = __ldg(row + tid);
        float4 v1 = __ldg(row + tid + TPB);
        acc0.x += v0.x; acc0.y += v0.y; acc0.z += v0.z; acc0.w += v0.w;
        acc1.x += v1.x; acc1.y += v1.y; acc1.z += v1.z; acc1.w += v1.w;
    }

    ((float4*)s_self)[tid]       = self0;
    ((float4*)s_self)[tid + TPB] = self1;
    ((float4*)s_mean)[tid]       = make_float4(acc0.x * inv, acc0.y * inv, acc0.z * inv, acc0.w * inv);
    ((float4*)s_mean)[tid + TPB] = make_float4(acc1.x * inv, acc1.y * inv, acc1.z * inv, acc1.w * inv);
    __syncthreads();

    // Phase 2: node output block = 2048*20 floats = 10240 float4s.
    // float4 idx -> float index idx*4; bs = idx/5; channels (idx%5)*4 .. +3.
    float4* ob = (float4*)out + (size_t)n * NFL4;
    #pragma unroll
    for (int it = 0; it < SITERS; it++) {
        int idx = it * TPB + tid;
        int bs  = idx / 5;
        int c0  = (idx % 5) * 4;
        float s = s_self[bs];
        float m = s_mean[bs];
        float4 r;
        { int c = c0 + 0; float b = (c < OUTF) ? s : m; r.x = fmaxf(b * sw[c], 0.0f); }
        { int c = c0 + 1; float b = (c < OUTF) ? s : m; r.y = fmaxf(b * sw[c], 0.0f); }
        { int c = c0 + 2; float b = (c < OUTF) ? s : m; r.z = fmaxf(b * sw[c], 0.0f); }
        { int c = c0 + 3; float b = (c < OUTF) ? s : m; r.w = fmaxf(b * sw[c], 0.0f); }
        __stcs(ob + idx, r);   // streaming store: keep features resident in L2
    }
}

extern "C" void kernel_launch(void* const* d_in, const int* in_sizes, int n_in,
                              void* d_out, int out_size) {
    const float* features = (const float*)d_in[0];
    const float* weight   = (const float*)d_in[1];
    const int*   edge_src = (const int*)d_in[2];
    const int*   edge_dst = (const int*)d_in[3];
    float*       out      = (float*)d_out;

    k_bucket<<<(NUM_EDGES + 511) / 512, 512>>>(edge_src, edge_dst);
    k_main<<<NUM_NODES, TPB>>>(features, weight, out);
}

// round 10
// speedup vs baseline: 1.8782x; 1.0145x over previous
#include <cuda_runtime.h>
#include <cuda_bf16.h>

#define NUM_NODES 5000
#define NUM_EDGES 80000
#define BS        2048      // BATCH * SEQ
#define OUTF      10
#define BKT_CAP   128       // max in-degree capacity (Poisson(16): P(>128) ~ 1e-60)
#define TPB       256
#define NFL4      (BS * 2 * OUTF / 4)      // 10240 float4 per node
#define SITERS    (NFL4 / TPB)             // 40 store iterations per node

// Scratch (allocation-free). g_cnt is zero-initialized at module load and
// self-cleaning: k_main resets g_cnt[n] after consuming it, so every call
// (correctness run, capture, every replay) sees g_cnt == 0 on entry.
__device__ int g_cnt[NUM_NODES];
__device__ int g_bkt[NUM_NODES * BKT_CAP];

// Vectorized bucket fill: each thread handles 4 edges (one int4 of src, one of dst).
// NUM_EDGES % 4 == 0. 4 independent atomic+store chains per thread -> MLP 4.
__global__ void k_bucket(const int* __restrict__ src, const int* __restrict__ dst) {
    int i = blockIdx.x * blockDim.x + threadIdx.x;          // quad index
    if (i < NUM_EDGES / 4) {
        int4 s4 = __ldg((const int4*)src + i);
        int4 d4 = __ldg((const int4*)dst + i);
        int p0 = atomicAdd(&g_cnt[d4.x], 1);
        int p1 = atomicAdd(&g_cnt[d4.y], 1);
        int p2 = atomicAdd(&g_cnt[d4.z], 1);
        int p3 = atomicAdd(&g_cnt[d4.w], 1);
        if (p0 < BKT_CAP) g_bkt[d4.x * BKT_CAP + p0] = s4.x;
        if (p1 < BKT_CAP) g_bkt[d4.y * BKT_CAP + p1] = s4.y;
        if (p2 < BKT_CAP) g_bkt[d4.z * BKT_CAP + p2] = s4.z;
        if (p3 < BKT_CAP) g_bkt[d4.w * BKT_CAP + p3] = s4.w;
    }
}

// One block per node (exact R5 body — proven local optimum).
// Phase 1: gather+mean into shared (thread owns 2 float4 lanes -> 2 indep load chains).
// Phase 2: fully-coalesced streaming output writes.
__global__ __launch_bounds__(TPB) void k_main(const float* __restrict__ f,
                                              const float* __restrict__ w,
                                              float* __restrict__ out) {
    const int n   = blockIdx.x;
    const int tid = threadIdx.x;

    __shared__ float sw[2 * OUTF];     // duplicated weight table: sw[c] = w[c % 10]
    __shared__ float s_self[BS];
    __shared__ float s_mean[BS];
    __shared__ int   sedge[BKT_CAP];

    if (tid < OUTF) { float wv = w[tid]; sw[tid] = wv; sw[tid + OUTF] = wv; }

    const int deg = min(g_cnt[n], BKT_CAP);
    const float inv = (deg > 0) ? (1.0f / (float)deg) : 0.0f;

    if (tid < deg) sedge[tid] = g_bkt[n * BKT_CAP + tid];
    __syncthreads();

    // Reset counter for the next graph replay (all reads of g_cnt[n] are done).
    if (tid == 0) g_cnt[n] = 0;

    // Two independent float4 lanes per thread: tid and tid+TPB (of BS/4=512 lanes).
    float4 acc0 = make_float4(0.f, 0.f, 0.f, 0.f);
    float4 acc1 = make_float4(0.f, 0.f, 0.f, 0.f);
    #pragma unroll 4
    for (int j = 0; j < deg; j++) {
        const float4* row = (const float4*)(f + (size_t)sedge[j] * BS);
        float4 v0 = __ldg(row + tid);
        float4 v1 = __ldg(row + tid + TPB);
        acc0.x += v0.x; acc0.y += v0.y; acc0.z += v0.z; acc0.w += v0.w;
        acc1.x += v1.x; acc1.y += v1.y; acc1.z += v1.z; acc1.w += v1.w;
    }

    const float4* selfrow = (const float4*)(f + (size_t)n * BS);
    float4 self0 = __ldg(selfrow + tid);
    float4 self1 = __ldg(selfrow + tid + TPB);

    ((float4*)s_self)[tid]       = self0;
    ((float4*)s_self)[tid + TPB] = self1;
    ((float4*)s_mean)[tid]       = make_float4(acc0.x * inv, acc0.y * inv, acc0.z * inv, acc0.w * inv);
    ((float4*)s_mean)[tid + TPB] = make_float4(acc1.x * inv, acc1.y * inv, acc1.z * inv, acc1.w * inv);
    __syncthreads();

    // Phase 2: node output block = 2048*20 floats = 10240 float4s.
    // float4 idx -> float index idx*4; bs = idx/5; channels (idx%5)*4 .. +3.
    float4* ob = (float4*)out + (size_t)n * NFL4;
    #pragma unroll
    for (int it = 0; it < SITERS; it++) {
        int idx = it * TPB + tid;
        int bs  = idx / 5;
        int c0  = (idx % 5) * 4;
        float s = s_self[bs];
        float m = s_mean[bs];
        float4 r;
        { int c = c0 + 0; float b = (c < OUTF) ? s : m; r.x = fmaxf(b * sw[c], 0.0f); }
        { int c = c0 + 1; float b = (c < OUTF) ? s : m; r.y = fmaxf(b * sw[c], 0.0f); }
        { int c = c0 + 2; float b = (c < OUTF) ? s : m; r.z = fmaxf(b * sw[c], 0.0f); }
        { int c = c0 + 3; float b = (c < OUTF) ? s : m; r.w = fmaxf(b * sw[c], 0.0f); }
        __stcs(ob + idx, r);   // streaming store: keep features resident in L2
    }
}

extern "C" void kernel_launch(void* const* d_in, const int* in_sizes, int n_in,
                              void* d_out, int out_size) {
    const float* features = (const float*)d_in[0];
    const float* weight   = (const float*)d_in[1];
    const int*   edge_src = (const int*)d_in[2];
    const int*   edge_dst = (const int*)d_in[3];
    float*       out      = (float*)d_out;

    k_bucket<<<(NUM_EDGES / 4 + 127) / 128, 128>>>(edge_src, edge_dst);
    k_main<<<NUM_NODES, TPB>>>(features, weight, out);
}

// round 11
// speedup vs baseline: 1.8973x; 1.0102x over previous
#include <cuda_runtime.h>
#include <cuda_bf16.h>

#define NUM_NODES 5000
#define NUM_EDGES 80000
#define BS        2048      // BATCH * SEQ
#define OUTF      10
#define BKT_CAP   128       // max in-degree capacity (Poisson(16): P(>128) ~ 1e-60)
#define TPB       256
#define NFL4      (BS * 2 * OUTF / 4)      // 10240 float4 per node
#define SITERS    (NFL4 / TPB)             // 40 store iterations per node

// Scratch (allocation-free). g_cnt is zero-initialized at module load and
// self-cleaning: k_main resets g_cnt[n] after consuming it, so every call
// (correctness run, capture, every replay) sees g_cnt == 0 on entry.
__device__ int g_cnt[NUM_NODES];
__device__ int g_bkt[NUM_NODES * BKT_CAP];

// Vectorized bucket fill: each thread handles 4 edges (one int4 of src, one of dst).
// NUM_EDGES % 4 == 0. 4 independent atomic+store chains per thread -> MLP 4.
__global__ void k_bucket(const int* __restrict__ src, const int* __restrict__ dst) {
    int i = blockIdx.x * blockDim.x + threadIdx.x;          // quad index
    if (i < NUM_EDGES / 4) {
        int4 s4 = __ldg((const int4*)src + i);
        int4 d4 = __ldg((const int4*)dst + i);
        int p0 = atomicAdd(&g_cnt[d4.x], 1);
        int p1 = atomicAdd(&g_cnt[d4.y], 1);
        int p2 = atomicAdd(&g_cnt[d4.z], 1);
        int p3 = atomicAdd(&g_cnt[d4.w], 1);
        if (p0 < BKT_CAP) g_bkt[d4.x * BKT_CAP + p0] = s4.x;
        if (p1 < BKT_CAP) g_bkt[d4.y * BKT_CAP + p1] = s4.y;
        if (p2 < BKT_CAP) g_bkt[d4.z * BKT_CAP + p2] = s4.z;
        if (p3 < BKT_CAP) g_bkt[d4.w * BKT_CAP + p3] = s4.w;
    }
}

// One block per node (exact R5 body — proven local optimum).
// Launched via PDL: grid ramps up while k_bucket drains; bucket-independent
// preamble runs before cudaGridDependencySynchronize().
__global__ __launch_bounds__(TPB) void k_main(const float* __restrict__ f,
                                              const float* __restrict__ w,
                                              float* __restrict__ out) {
    const int n   = blockIdx.x;
    const int tid = threadIdx.x;

    __shared__ float sw[2 * OUTF];     // duplicated weight table: sw[c] = w[c % 10]
    __shared__ float s_self[BS];
    __shared__ float s_mean[BS];
    __shared__ int   sedge[BKT_CAP];

    // Bucket-independent preamble (overlaps with k_bucket tail under PDL).
    if (tid < OUTF) { float wv = w[tid]; sw[tid] = wv; sw[tid + OUTF] = wv; }

#if __CUDA_ARCH__ >= 900
    cudaGridDependencySynchronize();   // k_bucket results now visible
#endif

    const int deg = min(g_cnt[n], BKT_CAP);
    const float inv = (deg > 0) ? (1.0f / (float)deg) : 0.0f;

    if (tid < deg) sedge[tid] = g_bkt[n * BKT_CAP + tid];
    __syncthreads();

    // Reset counter for the next graph replay (all reads of g_cnt[n] are done).
    if (tid == 0) g_cnt[n] = 0;

    // Two independent float4 lanes per thread: tid and tid+TPB (of BS/4=512 lanes).
    float4 acc0 = make_float4(0.f, 0.f, 0.f, 0.f);
    float4 acc1 = make_float4(0.f, 0.f, 0.f, 0.f);
    #pragma unroll 4
    for (int j = 0; j < deg; j++) {
        const float4* row = (const float4*)(f + (size_t)sedge[j] * BS);
        float4 v0 = __ldg(row + tid);
        float4 v1 = __ldg(row + tid + TPB);
        acc0.x += v0.x; acc0.y += v0.y; acc0.z += v0.z; acc0.w += v0.w;
        acc1.x += v1.x; acc1.y += v1.y; acc1.z += v1.z; acc1.w += v1.w;
    }

    const float4* selfrow = (const float4*)(f + (size_t)n * BS);
    float4 self0 = __ldg(selfrow + tid);
    float4 self1 = __ldg(selfrow + tid + TPB);

    ((float4*)s_self)[tid]       = self0;
    ((float4*)s_self)[tid + TPB] = self1;
    ((float4*)s_mean)[tid]       = make_float4(acc0.x * inv, acc0.y * inv, acc0.z * inv, acc0.w * inv);
    ((float4*)s_mean)[tid + TPB] = make_float4(acc1.x * inv, acc1.y * inv, acc1.z * inv, acc1.w * inv);
    __syncthreads();

    // Phase 2: node output block = 2048*20 floats = 10240 float4s.
    // float4 idx -> float index idx*4; bs = idx/5; channels (idx%5)*4 .. +3.
    float4* ob = (float4*)out + (size_t)n * NFL4;
    #pragma unroll
    for (int it = 0; it < SITERS; it++) {
        int idx = it * TPB + tid;
        int bs  = idx / 5;
        int c0  = (idx % 5) * 4;
        float s = s_self[bs];
        float m = s_mean[bs];
        float4 r;
        { int c = c0 + 0; float b = (c < OUTF) ? s : m; r.x = fmaxf(b * sw[c], 0.0f); }
        { int c = c0 + 1; float b = (c < OUTF) ? s : m; r.y = fmaxf(b * sw[c], 0.0f); }
        { int c = c0 + 2; float b = (c < OUTF) ? s : m; r.z = fmaxf(b * sw[c], 0.0f); }
        { int c = c0 + 3; float b = (c < OUTF) ? s : m; r.w = fmaxf(b * sw[c], 0.0f); }
        __stcs(ob + idx, r);   // streaming store: keep features resident in L2
    }
}

extern "C" void kernel_launch(void* const* d_in, const int* in_sizes, int n_in,
                              void* d_out, int out_size) {
    const float* features = (const float*)d_in[0];
    const float* weight   = (const float*)d_in[1];
    const int*   edge_src = (const int*)d_in[2];
    const int*   edge_dst = (const int*)d_in[3];
    float*       out      = (float*)d_out;

    k_bucket<<<(NUM_EDGES / 4 + 127) / 128, 128>>>(edge_src, edge_dst);

    // PDL launch of k_main: overlap its ramp-up with k_bucket's tail.
    cudaLaunchConfig_t cfg = {};
    cfg.gridDim  = dim3(NUM_NODES, 1, 1);
    cfg.blockDim = dim3(TPB, 1, 1);
    cfg.dynamicSmemBytes = 0;
    cfg.stream = 0;
    cudaLaunchAttribute attrs[1];
    attrs[0].id = cudaLaunchAttributeProgrammaticStreamSerialization;
    attrs[0].val.programmaticStreamSerializationAllowed = 1;
    cfg.attrs = attrs;
    cfg.numAttrs = 1;
    cudaLaunchKernelEx(&cfg, k_main, features, weight, out);
}